// round 15
// baseline (speedup 1.0000x reference)
#include <cuda_runtime.h>
#include <cuda_bf16.h>

// 3x3 PCF shadow visibility, 2 pixels per thread, 128-thread blocks.
// Window fetch = two aligned float2 loads per row; 32-bit gather offsets.
// Streaming reads (xy, depth) use __ldcs (read-once, evict-first).
// vis = (1/9) * sum sigmoid((zbuf[b, clamp(y+ii), clamp(x+jj)] - (z - 0.008)) * 1000)

__device__ __forceinline__ float ex2f(float x) {
    float y; asm("ex2.approx.f32 %0, %1;" : "=f"(y) : "f"(x)); return y;
}
__device__ __forceinline__ float rcpf(float x) {
    float y; asm("rcp.approx.f32 %0, %1;" : "=f"(y) : "f"(x)); return y;
}
__device__ __forceinline__ float quad_sum(float p0, float p1, float p2, float p3) {
    float a = p0 * p1, b = p2 * p3;
    return ((p0 + p1) * b + (p2 + p3) * a) * rcpf(a * b);
}
__device__ __forceinline__ float pval(float v, float C, float K) {
    float u = fmaf(-v, K, C);
    u = fminf(u, 30.0f);
    return 1.0f + ex2f(u);
}

__global__ __launch_bounds__(128) void shadow_pcf2_kernel(
    const float* __restrict__ zbuf,       // [N, S, S]
    const float* __restrict__ depth,      // [N, H, W, K]
    const int*   __restrict__ xy,         // [N, H, W, K, 2]
    const int*   __restrict__ image_size, // scalar S (device)
    float*       __restrict__ out,        // [N, H, W, K]
    int total,                            // N*H*W*K
    int zbuf_total)                       // N*S*S
{
    const int i    = blockIdx.x * blockDim.x + threadIdx.x;
    const int idx0 = 2 * i;
    if (idx0 >= total) return;

    // Uniform per-thread setup (no smem, no __syncthreads).
    const int S = __ldg(image_size);
    const unsigned SS = (unsigned)S * (unsigned)S;
    int N = (int)((unsigned)zbuf_total / SS);
    if (N < 1) N = 1;
    int HWK = total / N;
    if (HWK < 1) HWK = 1;

    const bool has2 = (idx0 + 1) < total;
    const float Kc = 1000.0f * 1.4426950408889634f;

    // batch index per pixel: pow2 shift (common case) or udiv
    int b_[2];
    if ((HWK & (HWK - 1)) == 0) {
        const int sh = __ffs(HWK) - 1;
        b_[0] = idx0 >> sh;
        b_[1] = (idx0 + 1) >> sh;
    } else {
        b_[0] = idx0 / HWK;
        b_[1] = (idx0 + 1) / HWK;
    }

    int xs[2], ys[2];
    float C_[2];
    if (has2) {
        int4   cc = __ldcs((const int4*)(xy + 2 * idx0));    // x0,y0,x1,y1 (read-once)
        float2 dd = __ldcs((const float2*)(depth + idx0));   // read-once
        xs[0] = cc.x; ys[0] = cc.y; xs[1] = cc.z; ys[1] = cc.w;
        C_[0] = (dd.x - 0.008f) * Kc;
        C_[1] = (dd.y - 0.008f) * Kc;
    } else {
        int2 cc = __ldcs((const int2*)(xy + 2 * idx0));
        xs[0] = cc.x; ys[0] = cc.y; xs[1] = 0; ys[1] = 0;
        C_[0] = (__ldcs(depth + idx0) - 0.008f) * Kc;
        C_[1] = 0.0f;
    }

    float acc[2] = {0.0f, 0.0f};

    if (((S & 1) == 0) && has2) {
        // ---- fast path (even S, rows 8B-aligned) ----
        // Taps are [c0, c0+2]; fetch floats [e8, e8+3] via two aligned float2
        // loads. Bounds: c0 in [0,S-3]; e8 = c0&~1 <= S-4 for even S, so
        // e8+3 <= S-1 always. Offsets kept as 32-bit element indices.
        unsigned off[2][3];
        bool d1_[2], lo_[2], hi_[2];

#pragma unroll
        for (int p = 0; p < 2; ++p) {
            const int x = xs[p], y = ys[p];
            const int ym = max(y - 1, 0);
            const int yp = min(y + 1, S - 1);
            const int xi = min(max(x, 1), S - 2);
            const int c0 = xi - 1;                // in [0, S-3]
            const int e8 = c0 & ~1;
            d1_[p] = (c0 & 1) != 0;
            lo_[p] = (x < 1);
            hi_[p] = (x > S - 2);
            const unsigned bb = (unsigned)b_[p] * SS + (unsigned)e8;
            off[p][0] = bb + (unsigned)ym * (unsigned)S;
            off[p][1] = bb + (unsigned)y  * (unsigned)S;
            off[p][2] = bb + (unsigned)yp * (unsigned)S;
        }

        // Issue all 12 gathers before any consumption (max MLP).
        float2 A[2][3], B[2][3];
#pragma unroll
        for (int p = 0; p < 2; ++p)
#pragma unroll
            for (int r = 0; r < 3; ++r) {
                A[p][r] = __ldg((const float2*)(zbuf + off[p][r]));
                B[p][r] = __ldg((const float2*)(zbuf + off[p][r] + 2));
            }

#pragma unroll
        for (int p = 0; p < 2; ++p) {
            const bool d1 = d1_[p], lo = lo_[p], hi = hi_[p];
            const float C = C_[p];
            float pv[9];
#pragma unroll
            for (int r = 0; r < 3; ++r) {
                // window values at [c0, c0+2]
                float t0 = d1 ? A[p][r].y : A[p][r].x;
                float t1 = d1 ? B[p][r].x : A[p][r].y;
                float t2 = d1 ? B[p][r].y : B[p][r].x;
                // remap for x==0 / x==S-1 edge clamping
                float vl = hi ? t1 : t0;
                float vm = lo ? t0 : (hi ? t2 : t1);
                float vr = lo ? t1 : t2;
                pv[3 * r + 0] = pval(vl, C, Kc);
                pv[3 * r + 1] = pval(vm, C, Kc);
                pv[3 * r + 2] = pval(vr, C, Kc);
            }
            acc[p] = quad_sum(pv[0], pv[1], pv[2], pv[3])
                   + quad_sum(pv[4], pv[5], pv[6], pv[7])
                   + rcpf(pv[8]);
        }

        float2 o = make_float2(acc[0] * (1.0f / 9.0f), acc[1] * (1.0f / 9.0f));
        *(float2*)(out + idx0) = o;
    } else {
        // ---- generic path (odd S or tail): scalar gathers, rolled ----
        for (int p = 0; p < 2; ++p) {
            const int idx = idx0 + p;
            if (p == 1 && !has2) break;
            const int x = xs[p], y = ys[p];
            const int xm = max(x - 1, 0), xp = min(x + 1, S - 1);
            const int ym = max(y - 1, 0), yp = min(y + 1, S - 1);
            const float* zb = zbuf + (size_t)b_[p] * (size_t)SS;
            const float C = C_[p];
            float a = 0.0f;
            int yy[3] = {ym, y, yp};
            for (int r = 0; r < 3; ++r) {
                const float* rr = zb + (size_t)(unsigned)yy[r] * (unsigned)S;
                a += rcpf(pval(__ldg(rr + xm), C, Kc));
                a += rcpf(pval(__ldg(rr + x ), C, Kc));
                a += rcpf(pval(__ldg(rr + xp), C, Kc));
            }
            out[idx] = a * (1.0f / 9.0f);
        }
    }
}

extern "C" void kernel_launch(void* const* d_in, const int* in_sizes, int n_in,
                              void* d_out, int out_size) {
    const float* zbuf   = (const float*)d_in[0];
    const float* depth  = (const float*)d_in[1];
    const int*   xy     = (const int*)  d_in[2];
    const int*   imsz   = (const int*)  d_in[3];
    float*       out    = (float*)d_out;

    const int total      = in_sizes[1];
    const int zbuf_total = in_sizes[0];

    const int threads = 128;
    const int pairs   = (total + 1) / 2;
    const int blocks  = (pairs + threads - 1) / threads;
    shadow_pcf2_kernel<<<blocks, threads>>>(zbuf, depth, xy, imsz, out,
                                            total, zbuf_total);
}